// round 12
// baseline (speedup 1.0000x reference)
#include <cuda_runtime.h>
#include <math.h>

// ---------------- problem constants ----------------
// B=4, C=3, H=W=768, P=128, S=64, K=31, n_h=n_w=11, N=121
#define TOTAL   7077888
#define IMGHW   589824
#define NPIX    961

typedef unsigned long long u64;

// ---------------- device scratch ----------------
__device__ float g_kern[363 * NPIX];      // flipped+normalized PSFs
__device__ float g_xlin[TOTAL];           // (relu(x)+eps)^gamma
__device__ float g_acc[4 * TOTAL];        // 4 parity planes (zero .bss; only valid entries written)

__device__ __forceinline__ float hannf(int r) {
    return 0.5f * (1.0f - __cosf((6.28318530717958647692f * (float)r) * 0.0078125f));
}
__device__ __forceinline__ double dpow_i(double x, int e) {
    double r = 1.0;
    for (int q = 0; q < e; q++) r *= x;
    return r;
}
__device__ __forceinline__ void ffma2(u64& acc, u64 k2, u64 w2) {
    asm("fma.rn.f32x2 %0, %1, %2, %0;" : "+l"(acc) : "l"(k2), "l"(w2));
}
__device__ __forceinline__ float u64lo(u64 v) { return __uint_as_float((unsigned)v); }
__device__ __forceinline__ float u64hi(u64 v) { return __uint_as_float((unsigned)(v >> 32)); }

__device__ __forceinline__ float blockReduce(float v, float* sm) {
    __syncthreads();
#pragma unroll
    for (int o = 16; o > 0; o >>= 1) v += __shfl_down_sync(0xffffffffu, v, o);
    int w = threadIdx.x >> 5;
    if ((threadIdx.x & 31) == 0) sm[w] = v;
    __syncthreads();
    if (threadIdx.x < 32) {
        float r = sm[threadIdx.x];
#pragma unroll
        for (int o = 16; o > 0; o >>= 1) r += __shfl_down_sync(0xffffffffu, r, o);
        if (threadIdx.x == 0) sm[32] = r;
    }
    __syncthreads();
    return sm[32];
}

// ---------------- stage 0: fused basis + MLP + PSF (unchanged exact numerics) ----------------
__global__ void setup_kernel(const float* __restrict__ w1, const float* __restrict__ b1,
                             const float* __restrict__ w2, const float* __restrict__ b2,
                             const float* __restrict__ w3, const float* __restrict__ b3) {
    __shared__ float red[33];
    __shared__ float s1[64], s2[64], scoef[14];
    __shared__ float fre[NPIX], fim[NPIX], Gre[NPIX], Gim[NPIX];
    __shared__ float twr[31], twi[31];

    int t = threadIdx.x;
    bool act = (t < NPIX);
    int blk = blockIdx.x;
    int n = blk / 3, c = blk % 3;

    {
        int iy = n / 11, jx = n % 11;
        float cy = (float)((((double)(iy * 64) + 64.0) / 768.0) * 2.0 - 1.0);
        float cx = (float)((((double)(jx * 64) + 64.0) / 768.0) * 2.0 - 1.0);
        if (t < 64) s1[t] = tanhf(cy * w1[t] + cx * w1[64 + t] + b1[t]);
        __syncthreads();
        if (t < 64) {
            float a = b2[t];
            for (int k = 0; k < 64; k++) a += s1[k] * w2[k * 64 + t];
            s2[t] = tanhf(a);
        }
        __syncthreads();
        if (t < 14) {
            float o = b3[t];
            for (int k = 0; k < 64; k++) o += s2[k] * w3[k * 14 + t];
            scoef[t] = o;
        }
        if (t < 31) {
            float ang = -6.28318530717958647692f * (float)t / 31.0f;
            twr[t] = cosf(ang);
            twi[t] = sinf(ang);
        }
        __syncthreads();
    }

    // numpy-exact linspace/r2 (no FMA contraction — 9-12-15 boundary pixels)
    int i = t / 31, j = t % 31;
    double step = 2.0 / 30.0;
    double x = 0.0, y = 0.0;
    float m = 0.0f;
    if (act) {
        x = (j == 30) ? 1.0 : __dadd_rn(__dmul_rn((double)j, step), -1.0);
        y = (i == 30) ? 1.0 : __dadd_rn(__dmul_rn((double)i, step), -1.0);
        double r2 = __dadd_rn(__dmul_rn(x, x), __dmul_rn(y, y));
        m = (r2 <= 1.0) ? 1.0f : 0.0f;
    }
    float mc = blockReduce(act ? m : 0.0f, red);

    float wl = 0.53f / ((c == 0) ? 0.61f : ((c == 1) ? 0.53f : 0.47f));
    float ph = 0.0f;
    int z = 0;
    for (int deg = 1; deg <= 4; deg++) {
        for (int k = 0; k <= deg; k++) {
            float bb = 0.0f;
            if (act) bb = (float)(dpow_i(x, deg - k) * dpow_i(y, k)) * m;
            float ss = blockReduce(bb * bb, red);
            float rms = sqrtf(ss / mc) + 1e-8f;
            if (act) ph = fmaf(scoef[z], bb / rms, ph);
            z++;
        }
    }

    if (act) {
        float th = 6.28318530717958647692f * (wl * ph);
        float sn, cs;
        sincosf(th, &sn, &cs);
        fre[t] = m * cs;
        fim[t] = m * sn;
    }
    __syncthreads();

    int u = t / 31, v = t % 31;
    if (act) {
        float gr = 0.0f, gi = 0.0f;
        int m2 = 0;
        for (int i2 = 0; i2 < 31; i2++) {
            float tr = twr[m2], ti = twi[m2];
            float ar = fre[i2 * 31 + v], ai = fim[i2 * 31 + v];
            gr = fmaf(ar, tr, gr); gr = fmaf(-ai, ti, gr);
            gi = fmaf(ar, ti, gi); gi = fmaf(ai, tr, gi);
            m2 += u; if (m2 >= 31) m2 -= 31;
        }
        Gre[t] = gr; Gim[t] = gi;
    }
    __syncthreads();

    float mag = 0.0f;
    if (act) {
        float fr = 0.0f, fi = 0.0f;
        int m2 = 0;
        for (int j2 = 0; j2 < 31; j2++) {
            float tr = twr[m2], ti = twi[m2];
            float gr = Gre[u * 31 + j2], gi = Gim[u * 31 + j2];
            fr = fmaf(gr, tr, fr); fr = fmaf(-gi, ti, fr);
            fi = fmaf(gr, ti, fi); fi = fmaf(gi, tr, fi);
            m2 += v; if (m2 >= 31) m2 -= 31;
        }
        mag = fr * fr + fi * fi;
    }
    float tot = blockReduce(act ? mag : 0.0f, red);
    float inv = 1.0f / (tot + 1e-6f);
    if (act) {
        int pu = u + 15; if (pu >= 31) pu -= 31;
        int pv = v + 15; if (pv >= 31) pv -= 31;
        g_kern[blk * NPIX + (30 - pu) * 31 + (30 - pv)] = mag * inv;
    }
}

// ---------------- stage 1: gamma-linearize ----------------
__global__ void prep_kernel(const float4* __restrict__ x, const float* __restrict__ gp) {
    int id = blockIdx.x * blockDim.x + threadIdx.x;
    float g = *gp;
    float4 v = x[id];
    float4 o;
    o.x = __expf(g * __logf(fmaxf(v.x, 0.0f) + 1e-6f));
    o.y = __expf(g * __logf(fmaxf(v.y, 0.0f) + 1e-6f));
    o.z = __expf(g * __logf(fmaxf(v.z, 0.0f) + 1e-6f));
    o.w = __expf(g * __logf(fmaxf(v.w, 0.0f) + 1e-6f));
    ((float4*)g_xlin)[id] = o;
}

// ---------------- stage 2: persistent double-buffered conv ----------------
#define CSTR    164
#define NITEMS  5808
#define NCTA    296
#define INBYTES (62 * CSTR * 4)            // 40672
#define KDOFF   INBYTES
#define BUFSZ   (INBYTES + 31 * 32 * 8)    // 48608
#define SMEM_CONV (2 * BUFSZ)              // 97216

__device__ __forceinline__ void item_decode(int id, int& C0, int& ip, int& jp,
                                            const float*& gxp, const float*& gk,
                                            float*& outp) {
    int tile = id & 3;
    int pcc = id >> 2;
    int c = pcc % 3;
    int t2 = pcc / 3;
    int n = t2 % 121;
    int b = t2 / 121;
    ip = n / 11; jp = n % 11;
    C0 = tile << 5;
    gxp = g_xlin + (size_t)(b * 3 + c) * IMGHW;
    gk  = g_kern + (n * 3 + c) * NPIX;
    int plane = ((ip & 1) << 1) | (jp & 1);
    outp = g_acc + (size_t)plane * TOTAL + (size_t)(b * 3 + c) * IMGHW;
}

extern __shared__ __align__(16) char csm[];

__global__ void __launch_bounds__(256, 2) conv_kernel() {
    int tid = threadIdx.x;
    int tx = tid & 31, ty = tid >> 5;
    int item = blockIdx.x;

    // ---- prologue: full fill of buffer 0 for first item ----
    {
        int C0, ip, jp;
        const float *gxp, *gk;
        float* outp;
        item_decode(item, C0, ip, jp, gxp, gk, outp);
        float* sInT = (float*)csm;
        float2* sKd = (float2*)(csm + KDOFF);
        for (int q = tid; q < NPIX; q += 256) {
            int dr = q / 31, dc2 = q - dr * 31;
            float k = gk[q];
            sKd[dc2 * 32 + dr] = make_float2(k, k);
        }
        for (int q = tid; q < 79 * 62; q += 256) {
            int rp = q / 62, cc = q - rp * 62;
            int sxx = C0 + cc - 15;
            int sy0 = 2 * rp - 15;
            float v0 = 0.0f, v1 = 0.0f;
            if ((unsigned)sxx < 128u) {
                const float* g = gxp + (ip * 64 + sy0) * 768 + jp * 64 + sxx;
                if ((unsigned)sy0 < 128u)       v0 = g[0];
                if ((unsigned)(sy0 + 1) < 128u) v1 = g[768];
            }
            u64 pk = (u64)__float_as_uint(v0) | ((u64)__float_as_uint(v1) << 32);
            *(u64*)(sInT + cc * CSTR + 2 * rp) = pk;
        }
    }
    __syncthreads();

    int bi = 0;
    while (true) {
        int C0, ip, jp;
        const float *gxp, *gk;
        float* outp;
        item_decode(item, C0, ip, jp, gxp, gk, outp);

        int nxt = item + NCTA;
        bool pf = (nxt < NITEMS);
        int C0n = 0, yb2 = 0, jb2 = 0;
        const float* gxp2 = 0;
        const float* gk2 = 0;
        if (pf) {
            int ipn, jpn;
            float* dmo;
            item_decode(nxt, C0n, ipn, jpn, gxp2, gk2, dmo);
            yb2 = ipn * 64; jb2 = jpn * 64;
        }
        float* sInT  = (float*)(csm + bi * BUFSZ);
        float2* sKd  = (float2*)(csm + bi * BUFSZ + KDOFF);
        char* bufN   = csm + (bi ^ 1) * BUFSZ;
        float2* sKdN = (float2*)(bufN + KDOFF);

        u64 A[8], O[9];
#pragma unroll
        for (int q = 0; q < 8; q++) A[q] = 0;
#pragma unroll
        for (int q = 0; q < 9; q++) O[q] = 0;

        float pv0[2], pv1[2], ptap[2];
        int pa[2], pta[2];

#pragma unroll 1
        for (int dc = 0; dc < 31; ++dc) {
            // ---- prefetch pipeline for next item (store stage first, then load) ----
            if (pf) {
                int s = dc & 1;
                if (dc >= 2 && dc < 22) {
                    if (pa[s] >= 0) {
                        u64 pk = (u64)__float_as_uint(pv0[s]) | ((u64)__float_as_uint(pv1[s]) << 32);
                        *(u64*)(bufN + pa[s]) = pk;
                    }
                }
                if (dc < 20) {
                    int q = tid + dc * 256;
                    if (q < 79 * 62) {
                        int rp = q / 62, cc = q - rp * 62;
                        int sxx = C0n + cc - 15;
                        int sy0 = 2 * rp - 15;
                        float v0 = 0.0f, v1 = 0.0f;
                        if ((unsigned)sxx < 128u) {
                            const float* g = gxp2 + (yb2 + sy0) * 768 + jb2 + sxx;
                            if ((unsigned)sy0 < 128u)       v0 = g[0];
                            if ((unsigned)(sy0 + 1) < 128u) v1 = g[768];
                        }
                        pv0[s] = v0; pv1[s] = v1;
                        pa[s] = (cc * CSTR + 2 * rp) * 4;
                    } else pa[s] = -1;
                }
                if (dc >= 24 && dc < 28) {
                    if (pta[s] >= 0) sKdN[pta[s]] = make_float2(ptap[s], ptap[s]);
                }
                if (dc >= 22 && dc < 26) {
                    int r = tid + (dc - 22) * 256;
                    if (r < NPIX) {
                        ptap[s] = gk2[r];
                        int drr = r / 31, dcc = r - drr * 31;
                        pta[s] = dcc * 32 + drr;
                    } else pta[s] = -1;
                }
            }

            // ---- FFMA2 mainloop body (identical math to R9) ----
            const u64* colp = (const u64*)(sInT + (tx + dc) * CSTR) + ty * 8;
            const ulonglong2* kp2 = (const ulonglong2*)(sKd + dc * 32);
            u64 pe[16];
#pragma unroll
            for (int m2 = 0; m2 < 5; m2++) {
                ulonglong2 w = ((const ulonglong2*)colp)[m2];
                pe[2 * m2] = w.x;
                pe[2 * m2 + 1] = w.y;
            }
#pragma unroll
            for (int d = 0; d < 15; d++) {
                ulonglong2 kk = kp2[d];
#pragma unroll
                for (int j = 0; j < 8; j++) ffma2(A[j], kk.x, pe[(d + j) & 15]);
#pragma unroll
                for (int j = 0; j < 9; j++) ffma2(O[j], kk.y, pe[(d + j) & 15]);
                if ((d & 1) == 0 && d <= 12) {
                    ulonglong2 w = ((const ulonglong2*)colp)[(d + 10) >> 1];
                    pe[(d + 10) & 15] = w.x;
                    pe[(d + 11) & 15] = w.y;
                }
            }
            {
                u64 ke = ((const u64*)kp2)[30];
#pragma unroll
                for (int j = 0; j < 8; j++) ffma2(A[j], ke, pe[(15 + j) & 15]);
            }
        }

        // ---- windowed output writes ----
        float hc = hannf(C0 + tx);
        int gx0 = jp * 64 + C0 + tx;
#pragma unroll
        for (int j = 0; j < 8; j++) {
            int pr0 = ty * 16 + 2 * j;
            float o0 = u64lo(A[j]) + u64hi(O[j]);
            float o1 = u64hi(A[j]) + u64lo(O[j + 1]);
            outp[(ip * 64 + pr0) * 768 + gx0]     = o0 * (hannf(pr0) * hc);
            outp[(ip * 64 + pr0 + 1) * 768 + gx0] = o1 * (hannf(pr0 + 1) * hc);
        }
        __syncthreads();
        if (!pf) break;
        item = nxt;
        bi ^= 1;
    }
}

// ---------------- stage 3: gather planes, window-normalize, inverse gamma ----------------
__global__ void fin_kernel(float4* __restrict__ out, const float* __restrict__ gp) {
    int id = blockIdx.x * blockDim.x + threadIdx.x;
    float ig = 1.0f / (*gp);
    int e0 = id * 4;
    int xc0 = e0 % 768;
    int y = (e0 / 768) % 768;

    float ny = 0.0f;
    int i1 = y >> 6;
    if (i1 <= 10) ny += hannf(y - i1 * 64);
    if (i1 >= 1)  ny += hannf(y - (i1 - 1) * 64);

    const float4* a0 = (const float4*)g_acc;
    float4 p0 = a0[id];
    float4 p1 = a0[(TOTAL >> 2) + id];
    float4 p2 = a0[(TOTAL >> 1) + id];
    float4 p3 = a0[3 * (TOTAL >> 2) + id];

    float4 r;
    float* rr = &r.x;
    const float* q0 = &p0.x; const float* q1 = &p1.x;
    const float* q2 = &p2.x; const float* q3 = &p3.x;
#pragma unroll
    for (int k = 0; k < 4; k++) {
        int xcol = xc0 + k;
        float nx = 0.0f;
        int j1 = xcol >> 6;
        if (j1 <= 10) nx += hannf(xcol - j1 * 64);
        if (j1 >= 1)  nx += hannf(xcol - (j1 - 1) * 64);
        float s = q0[k] + q1[k] + q2[k] + q3[k];
        float v = s / (ny * nx + 1e-6f);
        rr[k] = __expf(ig * __logf(fmaxf(v, 0.0f) + 1e-6f));
    }
    out[id] = r;
}

// ---------------- launch ----------------
extern "C" void kernel_launch(void* const* d_in, const int* in_sizes, int n_in,
                              void* d_out, int out_size) {
    const float* x  = (const float*)d_in[0];
    const float* w1 = (const float*)d_in[1];
    const float* b1 = (const float*)d_in[2];
    const float* w2 = (const float*)d_in[3];
    const float* b2 = (const float*)d_in[4];
    const float* w3 = (const float*)d_in[5];
    const float* b3 = (const float*)d_in[6];
    const float* gp = (const float*)d_in[7];

    static bool once = []() {
        cudaFuncSetAttribute(conv_kernel, cudaFuncAttributeMaxDynamicSharedMemorySize, SMEM_CONV);
        return true;
    }();
    (void)once;

    setup_kernel<<<363, 1024>>>(w1, b1, w2, b2, w3, b3);
    prep_kernel<<<(TOTAL / 4) / 256, 256>>>((const float4*)x, gp);
    conv_kernel<<<NCTA, 256, SMEM_CONV>>>();
    fin_kernel<<<(TOTAL / 4) / 256, 256>>>((float4*)d_out, gp);
}

// round 13
// speedup vs baseline: 1.0889x; 1.0889x over previous
#include <cuda_runtime.h>
#include <math.h>
#include <cstdint>

// ---------------- problem constants ----------------
// B=4, C=3, H=W=768, P=128, S=64, K=31, n_h=n_w=11, N=121
#define TOTAL   7077888
#define IMGHW   589824
#define NPIX    961

typedef unsigned long long u64;

// ---------------- device scratch ----------------
__device__ float g_kern[363 * NPIX];      // flipped+normalized PSFs
__device__ float g_xlin[TOTAL];           // (relu(x)+eps)^gamma
__device__ float g_acc[4 * TOTAL];        // 4 parity planes (zero .bss; only valid entries written)

__device__ __forceinline__ float hannf(int r) {
    return 0.5f * (1.0f - __cosf((6.28318530717958647692f * (float)r) * 0.0078125f));
}
__device__ __forceinline__ double dpow_i(double x, int e) {
    double r = 1.0;
    for (int q = 0; q < e; q++) r *= x;
    return r;
}
__device__ __forceinline__ void ffma2(u64& acc, u64 k2, u64 w2) {
    asm("fma.rn.f32x2 %0, %1, %2, %0;" : "+l"(acc) : "l"(k2), "l"(w2));
}
__device__ __forceinline__ float u64lo(u64 v) { return __uint_as_float((unsigned)v); }
__device__ __forceinline__ float u64hi(u64 v) { return __uint_as_float((unsigned)(v >> 32)); }

__device__ __forceinline__ uint32_t smem_u32(const void* p) {
    uint32_t a;
    asm("{ .reg .u64 t; cvta.to.shared.u64 t, %1; cvt.u32.u64 %0, t; }" : "=r"(a) : "l"(p));
    return a;
}
__device__ __forceinline__ void cp_async4(uint32_t daddr, const void* src, unsigned sz) {
    asm volatile("cp.async.ca.shared.global [%0], [%1], 4, %2;"
                 :: "r"(daddr), "l"(src), "r"(sz) : "memory");
}
#define CP_COMMIT() asm volatile("cp.async.commit_group;" ::: "memory")
#define CP_WAIT0()  asm volatile("cp.async.wait_group 0;" ::: "memory")

__device__ __forceinline__ float blockReduce(float v, float* sm) {
    __syncthreads();
#pragma unroll
    for (int o = 16; o > 0; o >>= 1) v += __shfl_down_sync(0xffffffffu, v, o);
    int w = threadIdx.x >> 5;
    if ((threadIdx.x & 31) == 0) sm[w] = v;
    __syncthreads();
    if (threadIdx.x < 32) {
        float r = sm[threadIdx.x];
#pragma unroll
        for (int o = 16; o > 0; o >>= 1) r += __shfl_down_sync(0xffffffffu, r, o);
        if (threadIdx.x == 0) sm[32] = r;
    }
    __syncthreads();
    return sm[32];
}

// ---------------- stage 0: fused basis + MLP + PSF (exact numerics, unchanged) ----------------
__global__ void setup_kernel(const float* __restrict__ w1, const float* __restrict__ b1,
                             const float* __restrict__ w2, const float* __restrict__ b2,
                             const float* __restrict__ w3, const float* __restrict__ b3) {
    __shared__ float red[33];
    __shared__ float s1[64], s2[64], scoef[14];
    __shared__ float fre[NPIX], fim[NPIX], Gre[NPIX], Gim[NPIX];
    __shared__ float twr[31], twi[31];

    int t = threadIdx.x;
    bool act = (t < NPIX);
    int blk = blockIdx.x;
    int n = blk / 3, c = blk % 3;

    {
        int iy = n / 11, jx = n % 11;
        float cy = (float)((((double)(iy * 64) + 64.0) / 768.0) * 2.0 - 1.0);
        float cx = (float)((((double)(jx * 64) + 64.0) / 768.0) * 2.0 - 1.0);
        if (t < 64) s1[t] = tanhf(cy * w1[t] + cx * w1[64 + t] + b1[t]);
        __syncthreads();
        if (t < 64) {
            float a = b2[t];
            for (int k = 0; k < 64; k++) a += s1[k] * w2[k * 64 + t];
            s2[t] = tanhf(a);
        }
        __syncthreads();
        if (t < 14) {
            float o = b3[t];
            for (int k = 0; k < 64; k++) o += s2[k] * w3[k * 14 + t];
            scoef[t] = o;
        }
        if (t < 31) {
            float ang = -6.28318530717958647692f * (float)t / 31.0f;
            twr[t] = cosf(ang);
            twi[t] = sinf(ang);
        }
        __syncthreads();
    }

    // numpy-exact linspace/r2 (no FMA contraction — 9-12-15 boundary pixels)
    int i = t / 31, j = t % 31;
    double step = 2.0 / 30.0;
    double x = 0.0, y = 0.0;
    float m = 0.0f;
    if (act) {
        x = (j == 30) ? 1.0 : __dadd_rn(__dmul_rn((double)j, step), -1.0);
        y = (i == 30) ? 1.0 : __dadd_rn(__dmul_rn((double)i, step), -1.0);
        double r2 = __dadd_rn(__dmul_rn(x, x), __dmul_rn(y, y));
        m = (r2 <= 1.0) ? 1.0f : 0.0f;
    }
    float mc = blockReduce(act ? m : 0.0f, red);

    float wl = 0.53f / ((c == 0) ? 0.61f : ((c == 1) ? 0.53f : 0.47f));
    float ph = 0.0f;
    int z = 0;
    for (int deg = 1; deg <= 4; deg++) {
        for (int k = 0; k <= deg; k++) {
            float bb = 0.0f;
            if (act) bb = (float)(dpow_i(x, deg - k) * dpow_i(y, k)) * m;
            float ss = blockReduce(bb * bb, red);
            float rms = sqrtf(ss / mc) + 1e-8f;
            if (act) ph = fmaf(scoef[z], bb / rms, ph);
            z++;
        }
    }

    if (act) {
        float th = 6.28318530717958647692f * (wl * ph);
        float sn, cs;
        sincosf(th, &sn, &cs);
        fre[t] = m * cs;
        fim[t] = m * sn;
    }
    __syncthreads();

    int u = t / 31, v = t % 31;
    if (act) {
        float gr = 0.0f, gi = 0.0f;
        int m2 = 0;
        for (int i2 = 0; i2 < 31; i2++) {
            float tr = twr[m2], ti = twi[m2];
            float ar = fre[i2 * 31 + v], ai = fim[i2 * 31 + v];
            gr = fmaf(ar, tr, gr); gr = fmaf(-ai, ti, gr);
            gi = fmaf(ar, ti, gi); gi = fmaf(ai, tr, gi);
            m2 += u; if (m2 >= 31) m2 -= 31;
        }
        Gre[t] = gr; Gim[t] = gi;
    }
    __syncthreads();

    float mag = 0.0f;
    if (act) {
        float fr = 0.0f, fi = 0.0f;
        int m2 = 0;
        for (int j2 = 0; j2 < 31; j2++) {
            float tr = twr[m2], ti = twi[m2];
            float gr = Gre[u * 31 + j2], gi = Gim[u * 31 + j2];
            fr = fmaf(gr, tr, fr); fr = fmaf(-gi, ti, fr);
            fi = fmaf(gr, ti, fi); fi = fmaf(gi, tr, fi);
            m2 += v; if (m2 >= 31) m2 -= 31;
        }
        mag = fr * fr + fi * fi;
    }
    float tot = blockReduce(act ? mag : 0.0f, red);
    float inv = 1.0f / (tot + 1e-6f);
    if (act) {
        int pu = u + 15; if (pu >= 31) pu -= 31;
        int pv = v + 15; if (pv >= 31) pv -= 31;
        g_kern[blk * NPIX + (30 - pu) * 31 + (30 - pv)] = mag * inv;
    }
}

// ---------------- stage 1: gamma-linearize ----------------
__global__ void prep_kernel(const float4* __restrict__ x, const float* __restrict__ gp) {
    int id = blockIdx.x * blockDim.x + threadIdx.x;
    float g = *gp;
    float4 v = x[id];
    float4 o;
    o.x = __expf(g * __logf(fmaxf(v.x, 0.0f) + 1e-6f));
    o.y = __expf(g * __logf(fmaxf(v.y, 0.0f) + 1e-6f));
    o.z = __expf(g * __logf(fmaxf(v.z, 0.0f) + 1e-6f));
    o.w = __expf(g * __logf(fmaxf(v.w, 0.0f) + 1e-6f));
    ((float4*)g_xlin)[id] = o;
}

// ---------------- stage 2: persistent conv with cp.async prefetch ----------------
#define CSTR    164
#define NITEMS  5808
#define NCTA    304
#define KD_OFF  (62 * CSTR * 4)                 // 40672
#define BUFSZ   (62 * CSTR * 4 + 31 * 32 * 8)   // 48608
#define SMEM_CONV (2 * BUFSZ)                   // 97216

__device__ __forceinline__ void item_decode(int id, int& C0, int& ip, int& jp,
                                            const float*& gxp, const float*& gk,
                                            float*& outp) {
    int tile = id & 3;
    int pcc = id >> 2;
    int c = pcc % 3;
    int t2 = pcc / 3;
    int n = t2 % 121;
    int b = t2 / 121;
    ip = n / 11; jp = n % 11;
    C0 = tile << 5;
    gxp = g_xlin + (size_t)(b * 3 + c) * IMGHW;
    gk  = g_kern + (n * 3 + c) * NPIX;
    int plane = ((ip & 1) << 1) | (jp & 1);
    outp = g_acc + (size_t)plane * TOTAL + (size_t)(b * 3 + c) * IMGHW;
}

extern __shared__ __align__(16) char csm[];

__global__ void __launch_bounds__(256) conv_kernel() {
    int tid = threadIdx.x;
    int tx = tid & 31, ty = tid >> 5;
    int item = blockIdx.x;

    // ---- prologue: plain full fill of buffer 0 for first item ----
    {
        int C0, ip, jp;
        const float *gxp, *gk;
        float* outp;
        item_decode(item, C0, ip, jp, gxp, gk, outp);
        float* sInT = (float*)csm;
        float2* sKd = (float2*)(csm + KD_OFF);
        for (int q = tid; q < NPIX; q += 256) {
            int dr = q / 31, dc2 = q - dr * 31;
            float k = gk[q];
            sKd[dc2 * 32 + dr] = make_float2(k, k);
        }
        for (int q = tid; q < 158 * 62; q += 256) {
            int rr = q / 62, cc = q - rr * 62;
            int sy = rr - 15, sx = C0 + cc - 15;
            float v = 0.0f;
            if ((unsigned)sy < 128u && (unsigned)sx < 128u)
                v = gxp[(ip * 64 + sy) * 768 + jp * 64 + sx];
            sInT[cc * CSTR + rr] = v;
        }
    }
    __syncthreads();

    int bi = 0;
    while (true) {
        int C0, ip, jp;
        const float *gxp, *gk;
        float* outp;
        item_decode(item, C0, ip, jp, gxp, gk, outp);

        int nxt = item + NCTA;
        bool pf = (nxt < NITEMS);

        float* sInT = (float*)(csm + bi * BUFSZ);
        float2* sKd = (float2*)(csm + bi * BUFSZ + KD_OFF);

        // ---- issue all prefetch for the next item BEFORE the mainloop ----
        if (pf) {
            int C0n, ipn, jpn;
            const float *gxp2, *gk2;
            float* dm;
            item_decode(nxt, C0n, ipn, jpn, gxp2, gk2, dm);
            char* bufN = csm + (bi ^ 1) * BUFSZ;
            uint32_t sbN = smem_u32(bufN);
            for (int q = tid; q < 158 * 62; q += 256) {
                int rr = q / 62, cc = q - rr * 62;
                int sy = rr - 15, sx = C0n + cc - 15;
                bool inb = ((unsigned)sy < 128u) && ((unsigned)sx < 128u);
                const float* src = gxp2 + (inb ? ((ipn * 64 + sy) * 768 + jpn * 64 + sx) : 0);
                cp_async4(sbN + (unsigned)(cc * CSTR + rr) * 4u, src, inb ? 4u : 0u);
            }
            CP_COMMIT();
            // taps for next item: plain dup fill (L2-hot, small); buf^1's sKd is idle this round
            float2* sKdN = (float2*)(bufN + KD_OFF);
            for (int q = tid; q < NPIX; q += 256) {
                int dr = q / 31, dc2 = q - dr * 31;
                float k = gk2[q];
                sKdN[dc2 * 32 + dr] = make_float2(k, k);
            }
        }

        // ---- FFMA2 mainloop (verbatim R9; zero prefetch pollution) ----
        u64 A[8], O[9];
#pragma unroll
        for (int q = 0; q < 8; q++) A[q] = 0;
#pragma unroll
        for (int q = 0; q < 9; q++) O[q] = 0;

#pragma unroll 1
        for (int dc = 0; dc < 31; ++dc) {
            const u64* colp = (const u64*)(sInT + (tx + dc) * CSTR) + ty * 8;
            const ulonglong2* kp2 = (const ulonglong2*)(sKd + dc * 32);
            u64 pe[16];
#pragma unroll
            for (int m2 = 0; m2 < 5; m2++) {
                ulonglong2 w = ((const ulonglong2*)colp)[m2];
                pe[2 * m2] = w.x;
                pe[2 * m2 + 1] = w.y;
            }
#pragma unroll
            for (int d = 0; d < 15; d++) {
                ulonglong2 kk = kp2[d];
#pragma unroll
                for (int j = 0; j < 8; j++) ffma2(A[j], kk.x, pe[(d + j) & 15]);
#pragma unroll
                for (int j = 0; j < 9; j++) ffma2(O[j], kk.y, pe[(d + j) & 15]);
                if ((d & 1) == 0 && d <= 12) {
                    ulonglong2 w = ((const ulonglong2*)colp)[(d + 10) >> 1];
                    pe[(d + 10) & 15] = w.x;
                    pe[(d + 11) & 15] = w.y;
                }
            }
            {
                u64 ke = ((const u64*)kp2)[30];
#pragma unroll
                for (int j = 0; j < 8; j++) ffma2(A[j], ke, pe[(15 + j) & 15]);
            }
        }

        // ---- windowed output writes ----
        float hc = hannf(C0 + tx);
        int gx0 = jp * 64 + C0 + tx;
#pragma unroll
        for (int j = 0; j < 8; j++) {
            int pr0 = ty * 16 + 2 * j;
            float o0 = u64lo(A[j]) + u64hi(O[j]);
            float o1 = u64hi(A[j]) + u64lo(O[j + 1]);
            outp[(ip * 64 + pr0) * 768 + gx0]     = o0 * (hannf(pr0) * hc);
            outp[(ip * 64 + pr0 + 1) * 768 + gx0] = o1 * (hannf(pr0 + 1) * hc);
        }

        if (!pf) break;
        CP_WAIT0();
        __syncthreads();
        item = nxt;
        bi ^= 1;
    }
}

// ---------------- stage 3: gather planes, window-normalize, inverse gamma ----------------
__global__ void fin_kernel(float4* __restrict__ out, const float* __restrict__ gp) {
    int id = blockIdx.x * blockDim.x + threadIdx.x;
    float ig = 1.0f / (*gp);
    int e0 = id * 4;
    int xc0 = e0 % 768;
    int y = (e0 / 768) % 768;

    float ny = 0.0f;
    int i1 = y >> 6;
    if (i1 <= 10) ny += hannf(y - i1 * 64);
    if (i1 >= 1)  ny += hannf(y - (i1 - 1) * 64);

    const float4* a0 = (const float4*)g_acc;
    float4 p0 = a0[id];
    float4 p1 = a0[(TOTAL >> 2) + id];
    float4 p2 = a0[(TOTAL >> 1) + id];
    float4 p3 = a0[3 * (TOTAL >> 2) + id];

    float4 r;
    float* rr = &r.x;
    const float* q0 = &p0.x; const float* q1 = &p1.x;
    const float* q2 = &p2.x; const float* q3 = &p3.x;
#pragma unroll
    for (int k = 0; k < 4; k++) {
        int xcol = xc0 + k;
        float nx = 0.0f;
        int j1 = xcol >> 6;
        if (j1 <= 10) nx += hannf(xcol - j1 * 64);
        if (j1 >= 1)  nx += hannf(xcol - (j1 - 1) * 64);
        float s = q0[k] + q1[k] + q2[k] + q3[k];
        float v = s / (ny * nx + 1e-6f);
        rr[k] = __expf(ig * __logf(fmaxf(v, 0.0f) + 1e-6f));
    }
    out[id] = r;
}

// ---------------- launch ----------------
extern "C" void kernel_launch(void* const* d_in, const int* in_sizes, int n_in,
                              void* d_out, int out_size) {
    const float* x  = (const float*)d_in[0];
    const float* w1 = (const float*)d_in[1];
    const float* b1 = (const float*)d_in[2];
    const float* w2 = (const float*)d_in[3];
    const float* b2 = (const float*)d_in[4];
    const float* w3 = (const float*)d_in[5];
    const float* b3 = (const float*)d_in[6];
    const float* gp = (const float*)d_in[7];

    static bool once = []() {
        cudaFuncSetAttribute(conv_kernel, cudaFuncAttributeMaxDynamicSharedMemorySize, SMEM_CONV);
        return true;
    }();
    (void)once;

    setup_kernel<<<363, 1024>>>(w1, b1, w2, b2, w3, b3);
    prep_kernel<<<(TOTAL / 4) / 256, 256>>>((const float4*)x, gp);
    conv_kernel<<<NCTA, 256, SMEM_CONV>>>();
    fin_kernel<<<(TOTAL / 4) / 256, 256>>>((float4*)d_out, gp);
}

// round 14
// speedup vs baseline: 1.1107x; 1.0199x over previous
#include <cuda_runtime.h>
#include <math.h>

// ---------------- problem constants ----------------
// B=4, C=3, H=W=768, P=128, S=64, K=31, n_h=n_w=11, N=121
#define TOTAL   7077888
#define IMGHW   589824
#define NPIX    961

typedef unsigned long long u64;

// ---------------- device scratch ----------------
__device__ float g_kern[363 * NPIX];      // flipped+normalized PSFs
__device__ float g_acc[4 * TOTAL];        // 4 parity planes (zero .bss; only valid entries written)

__device__ __forceinline__ float hannf(int r) {
    return 0.5f * (1.0f - __cosf((6.28318530717958647692f * (float)r) * 0.0078125f));
}
__device__ __forceinline__ double dpow_i(double x, int e) {
    double r = 1.0;
    for (int q = 0; q < e; q++) r *= x;
    return r;
}
__device__ __forceinline__ void ffma2(u64& acc, u64 k2, u64 w2) {
    asm("fma.rn.f32x2 %0, %1, %2, %0;" : "+l"(acc) : "l"(k2), "l"(w2));
}
__device__ __forceinline__ float u64lo(u64 v) { return __uint_as_float((unsigned)v); }
__device__ __forceinline__ float u64hi(u64 v) { return __uint_as_float((unsigned)(v >> 32)); }

__device__ __forceinline__ float blockReduce(float v, float* sm) {
    __syncthreads();
#pragma unroll
    for (int o = 16; o > 0; o >>= 1) v += __shfl_down_sync(0xffffffffu, v, o);
    int w = threadIdx.x >> 5;
    if ((threadIdx.x & 31) == 0) sm[w] = v;
    __syncthreads();
    if (threadIdx.x < 32) {
        float r = sm[threadIdx.x];
#pragma unroll
        for (int o = 16; o > 0; o >>= 1) r += __shfl_down_sync(0xffffffffu, r, o);
        if (threadIdx.x == 0) sm[32] = r;
    }
    __syncthreads();
    return sm[32];
}

// ---------------- stage 0: fused basis + MLP + PSF (exact numerics, unchanged) ----------------
__global__ void setup_kernel(const float* __restrict__ w1, const float* __restrict__ b1,
                             const float* __restrict__ w2, const float* __restrict__ b2,
                             const float* __restrict__ w3, const float* __restrict__ b3) {
    __shared__ float red[33];
    __shared__ float s1[64], s2[64], scoef[14];
    __shared__ float fre[NPIX], fim[NPIX], Gre[NPIX], Gim[NPIX];
    __shared__ float twr[31], twi[31];

    int t = threadIdx.x;
    bool act = (t < NPIX);
    int blk = blockIdx.x;
    int n = blk / 3, c = blk % 3;

    {
        int iy = n / 11, jx = n % 11;
        float cy = (float)((((double)(iy * 64) + 64.0) / 768.0) * 2.0 - 1.0);
        float cx = (float)((((double)(jx * 64) + 64.0) / 768.0) * 2.0 - 1.0);
        if (t < 64) s1[t] = tanhf(cy * w1[t] + cx * w1[64 + t] + b1[t]);
        __syncthreads();
        if (t < 64) {
            float a = b2[t];
            for (int k = 0; k < 64; k++) a += s1[k] * w2[k * 64 + t];
            s2[t] = tanhf(a);
        }
        __syncthreads();
        if (t < 14) {
            float o = b3[t];
            for (int k = 0; k < 64; k++) o += s2[k] * w3[k * 14 + t];
            scoef[t] = o;
        }
        if (t < 31) {
            float ang = -6.28318530717958647692f * (float)t / 31.0f;
            twr[t] = cosf(ang);
            twi[t] = sinf(ang);
        }
        __syncthreads();
    }

    // numpy-exact linspace/r2 (no FMA contraction — 9-12-15 boundary pixels)
    int i = t / 31, j = t % 31;
    double step = 2.0 / 30.0;
    double x = 0.0, y = 0.0;
    float m = 0.0f;
    if (act) {
        x = (j == 30) ? 1.0 : __dadd_rn(__dmul_rn((double)j, step), -1.0);
        y = (i == 30) ? 1.0 : __dadd_rn(__dmul_rn((double)i, step), -1.0);
        double r2 = __dadd_rn(__dmul_rn(x, x), __dmul_rn(y, y));
        m = (r2 <= 1.0) ? 1.0f : 0.0f;
    }
    float mc = blockReduce(act ? m : 0.0f, red);

    float wl = 0.53f / ((c == 0) ? 0.61f : ((c == 1) ? 0.53f : 0.47f));
    float ph = 0.0f;
    int z = 0;
    for (int deg = 1; deg <= 4; deg++) {
        for (int k = 0; k <= deg; k++) {
            float bb = 0.0f;
            if (act) bb = (float)(dpow_i(x, deg - k) * dpow_i(y, k)) * m;
            float ss = blockReduce(bb * bb, red);
            float rms = sqrtf(ss / mc) + 1e-8f;
            if (act) ph = fmaf(scoef[z], bb / rms, ph);
            z++;
        }
    }

    if (act) {
        float th = 6.28318530717958647692f * (wl * ph);
        float sn, cs;
        sincosf(th, &sn, &cs);
        fre[t] = m * cs;
        fim[t] = m * sn;
    }
    __syncthreads();

    int u = t / 31, v = t % 31;
    if (act) {
        float gr = 0.0f, gi = 0.0f;
        int m2 = 0;
        for (int i2 = 0; i2 < 31; i2++) {
            float tr = twr[m2], ti = twi[m2];
            float ar = fre[i2 * 31 + v], ai = fim[i2 * 31 + v];
            gr = fmaf(ar, tr, gr); gr = fmaf(-ai, ti, gr);
            gi = fmaf(ar, ti, gi); gi = fmaf(ai, tr, gi);
            m2 += u; if (m2 >= 31) m2 -= 31;
        }
        Gre[t] = gr; Gim[t] = gi;
    }
    __syncthreads();

    float mag = 0.0f;
    if (act) {
        float fr = 0.0f, fi = 0.0f;
        int m2 = 0;
        for (int j2 = 0; j2 < 31; j2++) {
            float tr = twr[m2], ti = twi[m2];
            float gr = Gre[u * 31 + j2], gi = Gim[u * 31 + j2];
            fr = fmaf(gr, tr, fr); fr = fmaf(-gi, ti, fr);
            fi = fmaf(gr, ti, fi); fi = fmaf(gi, tr, fi);
            m2 += v; if (m2 >= 31) m2 -= 31;
        }
        mag = fr * fr + fi * fi;
    }
    float tot = blockReduce(act ? mag : 0.0f, red);
    float inv = 1.0f / (tot + 1e-6f);
    if (act) {
        int pu = u + 15; if (pu >= 31) pu -= 31;
        int pv = v + 15; if (pv >= 31) pv -= 31;
        g_kern[blk * NPIX + (30 - pu) * 31 + (30 - pv)] = mag * inv;
    }
}

// ---------------- stage 1: 31x31 depthwise conv (R9 config) with inline gamma in fill ----------------
#define CSTR 164
__global__ void __launch_bounds__(256) conv_kernel(const float* __restrict__ xin,
                                                   const float* __restrict__ gp) {
    __shared__ __align__(16) float sInT[62 * CSTR];  // [col][row] transposed, 40.7 KB
    __shared__ __align__(16) float2 sKd[31 * 32];    // duplicated taps (k,k), [dc][dr], 7.9 KB

    int id = blockIdx.x;
    int tile = id & 3;
    int pcc = id >> 2;
    int c = pcc % 3;
    int t2 = pcc / 3;
    int n = t2 % 121;
    int b = t2 / 121;
    int ip = n / 11, jp = n % 11;
    int C0 = tile << 5;          // 0,32,64,96
    int tid = threadIdx.x;

    const float* gk = g_kern + (n * 3 + c) * NPIX;
    for (int q = tid; q < NPIX; q += 256) {
        int dr = q / 31, dc2 = q - dr * 31;
        float k = gk[q];
        sKd[dc2 * 32 + dr] = make_float2(k, k);
    }

    // fill with inline gamma-linearization (same op sequence the old prep used)
    float g = *gp;
    const float* gxp = xin + (size_t)(b * 3 + c) * IMGHW;
    for (int q = tid; q < 158 * 62; q += 256) {
        int rr = q / 62;
        int cc = q - rr * 62;
        int sy = rr - 15;
        int sx = C0 + cc - 15;
        float v = 0.0f;
        if ((unsigned)sy < 128u && (unsigned)sx < 128u) {
            float xv = gxp[(ip * 64 + sy) * 768 + jp * 64 + sx];
            v = __expf(g * __logf(fmaxf(xv, 0.0f) + 1e-6f));
        }
        sInT[cc * CSTR + rr] = v;
    }
    __syncthreads();

    int tx = tid & 31, ty = tid >> 5;    // ty 0..7 owns rows 16ty..16ty+15
    u64 A[8], O[9];
#pragma unroll
    for (int q = 0; q < 8; q++) A[q] = 0;
#pragma unroll
    for (int q = 0; q < 9; q++) O[q] = 0;

#pragma unroll 1
    for (int dc = 0; dc < 31; ++dc) {
        const u64* colp = (const u64*)(sInT + (tx + dc) * CSTR) + ty * 8;
        const ulonglong2* kp2 = (const ulonglong2*)(sKd + dc * 32);
        u64 pe[16];
#pragma unroll
        for (int m2 = 0; m2 < 5; m2++) {
            ulonglong2 w = ((const ulonglong2*)colp)[m2];
            pe[2 * m2] = w.x;
            pe[2 * m2 + 1] = w.y;
        }

#pragma unroll
        for (int d = 0; d < 15; d++) {
            ulonglong2 kk = kp2[d];          // (k_even[d], k_odd[d]) duplicated pairs
#pragma unroll
            for (int j = 0; j < 8; j++) ffma2(A[j], kk.x, pe[(d + j) & 15]);
#pragma unroll
            for (int j = 0; j < 9; j++) ffma2(O[j], kk.y, pe[(d + j) & 15]);
            if ((d & 1) == 0 && d <= 12) {   // refill elements d+10, d+11
                ulonglong2 w = ((const ulonglong2*)colp)[(d + 10) >> 1];
                pe[(d + 10) & 15] = w.x;
                pe[(d + 11) & 15] = w.y;
            }
        }
        {
            u64 ke = ((const u64*)kp2)[30];  // final even tap dr=30
#pragma unroll
            for (int j = 0; j < 8; j++) ffma2(A[j], ke, pe[(15 + j) & 15]);
        }
    }

    int plane = ((ip & 1) << 1) | (jp & 1);
    float hc = hannf(C0 + tx);
    int gx0 = jp * 64 + C0 + tx;
    float* outp = g_acc + (size_t)plane * TOTAL + (size_t)(b * 3 + c) * IMGHW;
#pragma unroll
    for (int j = 0; j < 8; j++) {
        int pr0 = ty * 16 + 2 * j;
        float o0 = u64lo(A[j]) + u64hi(O[j]);
        float o1 = u64hi(A[j]) + u64lo(O[j + 1]);
        outp[(ip * 64 + pr0) * 768 + gx0]     = o0 * (hannf(pr0) * hc);
        outp[(ip * 64 + pr0 + 1) * 768 + gx0] = o1 * (hannf(pr0 + 1) * hc);
    }
}

// ---------------- stage 2: gather planes, window-normalize, inverse gamma ----------------
__global__ void fin_kernel(float4* __restrict__ out, const float* __restrict__ gp) {
    int id = blockIdx.x * blockDim.x + threadIdx.x;
    float ig = 1.0f / (*gp);
    int e0 = id * 4;
    int xc0 = e0 % 768;
    int y = (e0 / 768) % 768;

    float ny = 0.0f;
    int i1 = y >> 6;
    if (i1 <= 10) ny += hannf(y - i1 * 64);
    if (i1 >= 1)  ny += hannf(y - (i1 - 1) * 64);

    const float4* a0 = (const float4*)g_acc;
    float4 p0 = a0[id];
    float4 p1 = a0[(TOTAL >> 2) + id];
    float4 p2 = a0[(TOTAL >> 1) + id];
    float4 p3 = a0[3 * (TOTAL >> 2) + id];

    float4 r;
    float* rr = &r.x;
    const float* q0 = &p0.x; const float* q1 = &p1.x;
    const float* q2 = &p2.x; const float* q3 = &p3.x;
#pragma unroll
    for (int k = 0; k < 4; k++) {
        int xcol = xc0 + k;
        float nx = 0.0f;
        int j1 = xcol >> 6;
        if (j1 <= 10) nx += hannf(xcol - j1 * 64);
        if (j1 >= 1)  nx += hannf(xcol - (j1 - 1) * 64);
        float s = q0[k] + q1[k] + q2[k] + q3[k];
        float v = s / (ny * nx + 1e-6f);
        rr[k] = __expf(ig * __logf(fmaxf(v, 0.0f) + 1e-6f));
    }
    out[id] = r;
}

// ---------------- launch ----------------
extern "C" void kernel_launch(void* const* d_in, const int* in_sizes, int n_in,
                              void* d_out, int out_size) {
    const float* x  = (const float*)d_in[0];
    const float* w1 = (const float*)d_in[1];
    const float* b1 = (const float*)d_in[2];
    const float* w2 = (const float*)d_in[3];
    const float* b2 = (const float*)d_in[4];
    const float* w3 = (const float*)d_in[5];
    const float* b3 = (const float*)d_in[6];
    const float* gp = (const float*)d_in[7];

    setup_kernel<<<363, 1024>>>(w1, b1, w2, b2, w3, b3);
    conv_kernel<<<5808, 256>>>(x, gp);
    fin_kernel<<<(TOTAL / 4) / 256, 256>>>((float4*)d_out, gp);
}

// round 15
// speedup vs baseline: 1.2368x; 1.1136x over previous
#include <cuda_runtime.h>
#include <math.h>

// ---------------- problem constants ----------------
// B=4, C=3, H=W=768, P=128, S=64, K=31, n_h=n_w=11, N=121
#define TOTAL   7077888
#define IMGHW   589824
#define NPIX    961

typedef unsigned long long u64;

// ---------------- device scratch ----------------
__device__ float g_basis[14 * NPIX];      // rms-normalized basis (constants)
__device__ float g_mask[NPIX];
__device__ float g_coeffs[121 * 14];
__device__ float g_kern[363 * NPIX];      // flipped+normalized PSFs
__device__ float g_xlin[TOTAL];           // (relu(x)+eps)^gamma
__device__ float g_acc[4 * TOTAL];        // 4 parity planes (zero .bss; only valid entries written)

__device__ __forceinline__ float hannf(int r) {
    return 0.5f * (1.0f - __cosf((6.28318530717958647692f * (float)r) * 0.0078125f));
}
__device__ __forceinline__ double dpow_i(double x, int e) {
    double r = 1.0;
    for (int q = 0; q < e; q++) r *= x;
    return r;
}
__device__ __forceinline__ void ffma2(u64& acc, u64 k2, u64 w2) {
    asm("fma.rn.f32x2 %0, %1, %2, %0;" : "+l"(acc) : "l"(k2), "l"(w2));
}
__device__ __forceinline__ float u64lo(u64 v) { return __uint_as_float((unsigned)v); }
__device__ __forceinline__ float u64hi(u64 v) { return __uint_as_float((unsigned)(v >> 32)); }

// ---------------- stage 0a: pupil basis, computed ONCE (1 block) ----------------
// CRITICAL numerics: numpy-exact IEEE sequence (no FMA contraction) — 16 pixels sit
// EXACTLY on r2==1 (9-12-15 triple); membership decided by last-ulp rounding.
__global__ void basis_kernel() {
    __shared__ float red[1024];
    int t = threadIdx.x;
    bool act = (t < NPIX);
    int i = t / 31, j = t % 31;

    double step = 2.0 / 30.0;
    double x = 0.0, y = 0.0;
    float m = 0.0f;
    if (act) {
        x = (j == 30) ? 1.0 : __dadd_rn(__dmul_rn((double)j, step), -1.0);
        y = (i == 30) ? 1.0 : __dadd_rn(__dmul_rn((double)i, step), -1.0);
        double r2 = __dadd_rn(__dmul_rn(x, x), __dmul_rn(y, y));
        m = (r2 <= 1.0) ? 1.0f : 0.0f;
        g_mask[t] = m;
    }
    red[t] = act ? m : 0.0f;
    __syncthreads();
    for (int s = 512; s > 0; s >>= 1) {
        if (t < s) red[t] += red[t + s];
        __syncthreads();
    }
    float mc = red[0];
    __syncthreads();

    int z = 0;
    for (int deg = 1; deg <= 4; deg++) {
        for (int k = 0; k <= deg; k++) {
            float bb = 0.0f;
            if (act) bb = (float)(dpow_i(x, deg - k) * dpow_i(y, k)) * m;
            red[t] = bb * bb;
            __syncthreads();
            for (int s = 512; s > 0; s >>= 1) {
                if (t < s) red[t] += red[t + s];
                __syncthreads();
            }
            float rms = sqrtf(red[0] / mc) + 1e-8f;
            __syncthreads();
            if (act) g_basis[z * NPIX + t] = bb / rms;
            z++;
        }
    }
}

// ---------------- stage 0b: MLP -> zernike coeffs ----------------
__global__ void mlp_kernel(const float* __restrict__ w1, const float* __restrict__ b1,
                           const float* __restrict__ w2, const float* __restrict__ b2,
                           const float* __restrict__ w3, const float* __restrict__ b3) {
    __shared__ float s1[64], s2[64];
    int n = blockIdx.x;
    int t = threadIdx.x;
    int iy = n / 11, jx = n % 11;
    float cy = (float)((((double)(iy * 64) + 64.0) / 768.0) * 2.0 - 1.0);
    float cx = (float)((((double)(jx * 64) + 64.0) / 768.0) * 2.0 - 1.0);

    float h = tanhf(cy * w1[t] + cx * w1[64 + t] + b1[t]);
    s1[t] = h;
    __syncthreads();
    float a = b2[t];
    for (int k = 0; k < 64; k++) a += s1[k] * w2[k * 64 + t];
    s2[t] = tanhf(a);
    __syncthreads();
    if (t < 14) {
        float o = b3[t];
        for (int k = 0; k < 64; k++) o += s2[k] * w3[k * 14 + t];
        g_coeffs[n * 14 + t] = o;
    }
}

// ---------------- stage 0c: PSF via 31x31 separable DFT (one reduction) ----------------
__global__ void psf_kernel() {
    __shared__ float fre[NPIX], fim[NPIX], Gre[NPIX], Gim[NPIX];
    __shared__ float twr[31], twi[31], scoef[14], red[33];
    int t = threadIdx.x;
    bool act = (t < NPIX);
    int blk = blockIdx.x;            // n*3 + c
    int n = blk / 3, c = blk % 3;

    if (t < 31) {
        float ang = -6.28318530717958647692f * (float)t / 31.0f;
        twr[t] = cosf(ang);
        twi[t] = sinf(ang);
    }
    if (t < 14) scoef[t] = g_coeffs[n * 14 + t];
    __syncthreads();

    float wl = 0.53f / ((c == 0) ? 0.61f : ((c == 1) ? 0.53f : 0.47f));
    if (act) {
        float ph = 0.0f;
#pragma unroll
        for (int z = 0; z < 14; z++) ph = fmaf(scoef[z], g_basis[z * NPIX + t], ph);
        float th = 6.28318530717958647692f * (wl * ph);
        float sn, cs;
        sincosf(th, &sn, &cs);
        float m = g_mask[t];
        fre[t] = m * cs;
        fim[t] = m * sn;
    }
    __syncthreads();

    int u = t / 31, v = t % 31;
    if (act) {
        float gr = 0.0f, gi = 0.0f;
        int m2 = 0;
        for (int i2 = 0; i2 < 31; i2++) {
            float tr = twr[m2], ti = twi[m2];
            float ar = fre[i2 * 31 + v], ai = fim[i2 * 31 + v];
            gr = fmaf(ar, tr, gr); gr = fmaf(-ai, ti, gr);
            gi = fmaf(ar, ti, gi); gi = fmaf(ai, tr, gi);
            m2 += u; if (m2 >= 31) m2 -= 31;
        }
        Gre[t] = gr; Gim[t] = gi;
    }
    __syncthreads();

    float mag = 0.0f;
    if (act) {
        float fr = 0.0f, fi = 0.0f;
        int m2 = 0;
        for (int j2 = 0; j2 < 31; j2++) {
            float tr = twr[m2], ti = twi[m2];
            float gr = Gre[u * 31 + j2], gi = Gim[u * 31 + j2];
            fr = fmaf(gr, tr, fr); fr = fmaf(-gi, ti, fr);
            fi = fmaf(gr, ti, fi); fi = fmaf(gi, tr, fi);
            m2 += v; if (m2 >= 31) m2 -= 31;
        }
        mag = fr * fr + fi * fi;
    }
    // one shuffle-based block reduction
    {
        float vsum = act ? mag : 0.0f;
#pragma unroll
        for (int o = 16; o > 0; o >>= 1) vsum += __shfl_down_sync(0xffffffffu, vsum, o);
        int w = t >> 5;
        if ((t & 31) == 0) red[w] = vsum;
        __syncthreads();
        if (t < 32) {
            float r = red[t];
#pragma unroll
            for (int o = 16; o > 0; o >>= 1) r += __shfl_down_sync(0xffffffffu, r, o);
            if (t == 0) red[32] = r;
        }
        __syncthreads();
    }
    float inv = 1.0f / (red[32] + 1e-6f);
    if (act) {
        int pu = u + 15; if (pu >= 31) pu -= 31;   // fftshift
        int pv = v + 15; if (pv >= 31) pv -= 31;
        g_kern[blk * NPIX + (30 - pu) * 31 + (30 - pv)] = mag * inv;  // flip
    }
}

// ---------------- stage 1: gamma-linearize (float4 + fast pow) ----------------
__global__ void prep_kernel(const float4* __restrict__ x, const float* __restrict__ gp) {
    int id = blockIdx.x * blockDim.x + threadIdx.x;
    float g = *gp;
    float4 v = x[id];
    float4 o;
    o.x = __expf(g * __logf(fmaxf(v.x, 0.0f) + 1e-6f));
    o.y = __expf(g * __logf(fmaxf(v.y, 0.0f) + 1e-6f));
    o.z = __expf(g * __logf(fmaxf(v.z, 0.0f) + 1e-6f));
    o.w = __expf(g * __logf(fmaxf(v.w, 0.0f) + 1e-6f));
    ((float4*)g_xlin)[id] = o;
}

// ---------------- stage 2: 31x31 depthwise conv (verbatim R9 champion) ----------------
#define CSTR 164
__global__ void __launch_bounds__(256) conv_kernel() {
    __shared__ __align__(16) float sInT[62 * CSTR];  // [col][row] transposed, 40.7 KB
    __shared__ __align__(16) float2 sKd[31 * 32];    // duplicated taps (k,k), [dc][dr], 7.9 KB

    int id = blockIdx.x;
    int tile = id & 3;
    int pcc = id >> 2;
    int c = pcc % 3;
    int t2 = pcc / 3;
    int n = t2 % 121;
    int b = t2 / 121;
    int ip = n / 11, jp = n % 11;
    int C0 = tile << 5;          // 0,32,64,96
    int tid = threadIdx.x;

    const float* gk = g_kern + (n * 3 + c) * NPIX;
    for (int q = tid; q < NPIX; q += 256) {
        int dr = q / 31, dc2 = q - dr * 31;
        float k = gk[q];
        sKd[dc2 * 32 + dr] = make_float2(k, k);
    }

    const float* gxp = g_xlin + (size_t)(b * 3 + c) * IMGHW;
    for (int q = tid; q < 158 * 62; q += 256) {
        int rr = q / 62;
        int cc = q - rr * 62;
        int sy = rr - 15;
        int sx = C0 + cc - 15;
        float v = 0.0f;
        if ((unsigned)sy < 128u && (unsigned)sx < 128u)
            v = gxp[(ip * 64 + sy) * 768 + (jp * 64 + sx)];
        sInT[cc * CSTR + rr] = v;
    }
    __syncthreads();

    int tx = tid & 31, ty = tid >> 5;    // ty 0..7 owns rows 16ty..16ty+15
    u64 A[8], O[9];
#pragma unroll
    for (int q = 0; q < 8; q++) A[q] = 0;
#pragma unroll
    for (int q = 0; q < 9; q++) O[q] = 0;

#pragma unroll 1
    for (int dc = 0; dc < 31; ++dc) {
        const u64* colp = (const u64*)(sInT + (tx + dc) * CSTR) + ty * 8;
        const ulonglong2* kp2 = (const ulonglong2*)(sKd + dc * 32);
        u64 pe[16];
#pragma unroll
        for (int m2 = 0; m2 < 5; m2++) {
            ulonglong2 w = ((const ulonglong2*)colp)[m2];
            pe[2 * m2] = w.x;
            pe[2 * m2 + 1] = w.y;
        }

#pragma unroll
        for (int d = 0; d < 15; d++) {
            ulonglong2 kk = kp2[d];          // (k_even[d], k_odd[d]) duplicated pairs
#pragma unroll
            for (int j = 0; j < 8; j++) ffma2(A[j], kk.x, pe[(d + j) & 15]);
#pragma unroll
            for (int j = 0; j < 9; j++) ffma2(O[j], kk.y, pe[(d + j) & 15]);
            if ((d & 1) == 0 && d <= 12) {   // refill elements d+10, d+11
                ulonglong2 w = ((const ulonglong2*)colp)[(d + 10) >> 1];
                pe[(d + 10) & 15] = w.x;
                pe[(d + 11) & 15] = w.y;
            }
        }
        {
            u64 ke = ((const u64*)kp2)[30];  // final even tap dr=30
#pragma unroll
            for (int j = 0; j < 8; j++) ffma2(A[j], ke, pe[(15 + j) & 15]);
        }
    }

    int plane = ((ip & 1) << 1) | (jp & 1);
    float hc = hannf(C0 + tx);
    int gx0 = jp * 64 + C0 + tx;
    float* outp = g_acc + (size_t)plane * TOTAL + (size_t)(b * 3 + c) * IMGHW;
#pragma unroll
    for (int j = 0; j < 8; j++) {
        int pr0 = ty * 16 + 2 * j;
        float o0 = u64lo(A[j]) + u64hi(O[j]);
        float o1 = u64hi(A[j]) + u64lo(O[j + 1]);
        outp[(ip * 64 + pr0) * 768 + gx0]     = o0 * (hannf(pr0) * hc);
        outp[(ip * 64 + pr0 + 1) * 768 + gx0] = o1 * (hannf(pr0 + 1) * hc);
    }
}

// ---------------- stage 3: gather planes, window-normalize, inverse gamma ----------------
__global__ void fin_kernel(float4* __restrict__ out, const float* __restrict__ gp) {
    int id = blockIdx.x * blockDim.x + threadIdx.x;
    float ig = 1.0f / (*gp);
    int e0 = id * 4;
    int xc0 = e0 % 768;
    int y = (e0 / 768) % 768;

    float ny = 0.0f;
    int i1 = y >> 6;
    if (i1 <= 10) ny += hannf(y - i1 * 64);
    if (i1 >= 1)  ny += hannf(y - (i1 - 1) * 64);

    const float4* a0 = (const float4*)g_acc;
    float4 p0 = a0[id];
    float4 p1 = a0[(TOTAL >> 2) + id];
    float4 p2 = a0[(TOTAL >> 1) + id];
    float4 p3 = a0[3 * (TOTAL >> 2) + id];

    float4 r;
    float* rr = &r.x;
    const float* q0 = &p0.x; const float* q1 = &p1.x;
    const float* q2 = &p2.x; const float* q3 = &p3.x;
#pragma unroll
    for (int k = 0; k < 4; k++) {
        int xcol = xc0 + k;
        float nx = 0.0f;
        int j1 = xcol >> 6;
        if (j1 <= 10) nx += hannf(xcol - j1 * 64);
        if (j1 >= 1)  nx += hannf(xcol - (j1 - 1) * 64);
        float s = q0[k] + q1[k] + q2[k] + q3[k];
        float v = s / (ny * nx + 1e-6f);
        rr[k] = __expf(ig * __logf(fmaxf(v, 0.0f) + 1e-6f));
    }
    out[id] = r;
}

// ---------------- launch ----------------
extern "C" void kernel_launch(void* const* d_in, const int* in_sizes, int n_in,
                              void* d_out, int out_size) {
    const float* x  = (const float*)d_in[0];
    const float* w1 = (const float*)d_in[1];
    const float* b1 = (const float*)d_in[2];
    const float* w2 = (const float*)d_in[3];
    const float* b2 = (const float*)d_in[4];
    const float* w3 = (const float*)d_in[5];
    const float* b3 = (const float*)d_in[6];
    const float* gp = (const float*)d_in[7];

    basis_kernel<<<1, 1024>>>();
    mlp_kernel<<<121, 64>>>(w1, b1, w2, b2, w3, b3);
    psf_kernel<<<363, 1024>>>();
    prep_kernel<<<(TOTAL / 4) / 256, 256>>>((const float4*)x, gp);
    conv_kernel<<<5808, 256>>>();
    fin_kernel<<<(TOTAL / 4) / 256, 256>>>((float4*)d_out, gp);
}